// round 12
// baseline (speedup 1.0000x reference)
#include <cuda_runtime.h>

// ChamferLoss: B=8, N=M=8192, D=3 fp32, inputs ~ N(0,1).
// out = mean_n min_m ||gt_n - pred_m||^2 + mean_m min_n ||pred_m - gt_n||^2
//
// Grid-accelerated exact NN (R10 pivot). R11 finding: k_query was ~140us of
// the 168us total because its branchy shell loop compiled to MLP~1 candidate
// loads served from L2 (~250cyc each). R11 change: regular two-phase query.
//  Phase 1: every query scans its full 3x3x3 cell neighborhood as 9 x-runs,
//           run bounds all loaded upfront, candidate loop manually 4-unrolled
//           (4 independent LDG.128 + independent d2 trees -> MLP>=4).
//  Phase 2: only if best > h^2 (~2-4% of queries, bound: any unscanned point
//           is >= h away) -> expanding Chebyshev shells from ring 2.
// Exact min; per-point results written to original indices -> deterministic.

#define BATCH   8
#define NPTS    8192
#define G       32
#define CELLS   (G * G * G)
#define NSB     (2 * BATCH)            // (side,batch) slots; side 0=gts 1=preds
#define RANGE   6.0f                   // grid covers [-6,6]^3; max|coord|~4.7
#define HCELL   (2.0f * RANGE / G)     // 0.375
#define INVH    ((float)G / (2.0f * RANGE))
#define NTOT    (NSB * NPTS)           // 131072 points total
#define FINF    3.402823466e+38f

__device__ int    g_count [NSB * CELLS];
__device__ int    g_cursor[NSB * CELLS];
__device__ int    g_offs  [NSB * (CELLS + 1)];
__device__ float4 g_sorted[NSB * NPTS];         // cell-sorted, .w = orig idx
__device__ float  g_minbuf[NSB * NPTS];         // min d2 by original index
__device__ float  g_blocksums[512];

__device__ __forceinline__ int cell_of(float x, float y, float z,
                                       int& cx, int& cy, int& cz) {
    cx = min(G - 1, max(0, (int)floorf((x + RANGE) * INVH)));
    cy = min(G - 1, max(0, (int)floorf((y + RANGE) * INVH)));
    cz = min(G - 1, max(0, (int)floorf((z + RANGE) * INVH)));
    return (cz * G + cy) * G + cx;
}

__device__ __forceinline__ float dist2(float4 q, float4 p) {
    float dx = q.x - p.x, dy = q.y - p.y, dz = q.z - p.z;
    return dx * dx + dy * dy + dz * dz;
}

// 1. zero counts + cursors
__global__ __launch_bounds__(256)
void k_zero() {
    int i = blockIdx.x * 256 + threadIdx.x;
    int n = NSB * CELLS;
    for (; i < 2 * n; i += gridDim.x * 256) {
        if (i < n) g_count[i] = 0;
        else       g_cursor[i - n] = 0;
    }
}

// 2. count points per cell
__global__ __launch_bounds__(256)
void k_count(const float* __restrict__ gts, const float* __restrict__ preds) {
    int idx = blockIdx.x * 256 + threadIdx.x;
    int sb  = idx >> 13;
    int i   = idx & (NPTS - 1);
    int side = sb >> 3, b = sb & 7;
    const float* p = (side == 0 ? gts : preds) + ((size_t)b * NPTS + i) * 3;
    int cx, cy, cz;
    int c = cell_of(p[0], p[1], p[2], cx, cy, cz);
    atomicAdd(&g_count[sb * CELLS + c], 1);
}

// 3. exclusive prefix sum per (side,batch): 16 blocks x 1024 threads
__global__ __launch_bounds__(1024)
void k_scan() {
    const int sb = blockIdx.x;
    const int t  = threadIdx.x;
    const int base = sb * CELLS + t * 32;

    int s = 0;
#pragma unroll
    for (int k = 0; k < 32; ++k) s += g_count[base + k];

    __shared__ int ws[32];
    int lane = t & 31, wid = t >> 5;
    int v = s;
#pragma unroll
    for (int d = 1; d < 32; d <<= 1) {
        int n = __shfl_up_sync(0xFFFFFFFFu, v, d);
        if (lane >= d) v += n;
    }
    if (lane == 31) ws[wid] = v;
    __syncthreads();
    if (wid == 0) {
        int w = ws[lane];
#pragma unroll
        for (int d = 1; d < 32; d <<= 1) {
            int n = __shfl_up_sync(0xFFFFFFFFu, w, d);
            if (lane >= d) w += n;
        }
        ws[lane] = w;
    }
    __syncthreads();
    int excl = v - s + (wid ? ws[wid - 1] : 0);

    int run = excl;
    int obase = sb * (CELLS + 1) + t * 32;
#pragma unroll
    for (int k = 0; k < 32; ++k) {
        g_offs[obase + k] = run;
        run += g_count[base + k];
    }
    if (t == 1023) g_offs[sb * (CELLS + 1) + CELLS] = run;
}

// 4. scatter points into cell-sorted order
__global__ __launch_bounds__(256)
void k_scatter(const float* __restrict__ gts, const float* __restrict__ preds) {
    int idx = blockIdx.x * 256 + threadIdx.x;
    int sb  = idx >> 13;
    int i   = idx & (NPTS - 1);
    int side = sb >> 3, b = sb & 7;
    const float* p = (side == 0 ? gts : preds) + ((size_t)b * NPTS + i) * 3;
    float x = p[0], y = p[1], z = p[2];
    int cx, cy, cz;
    int c = cell_of(x, y, z, cx, cy, cz);
    int pos = g_offs[sb * (CELLS + 1) + c] + atomicAdd(&g_cursor[sb * CELLS + c], 1);
    g_sorted[sb * NPTS + pos] = make_float4(x, y, z, __int_as_float(i));
}

// 5. exact NN query, two-phase
__global__ __launch_bounds__(256)
void k_query() {
    int idx  = blockIdx.x * 256 + threadIdx.x;
    int qsb  = idx >> 13;
    int slot = idx & (NPTS - 1);
    int gsb  = qsb ^ 8;

    float4 q = g_sorted[qsb * NPTS + slot];
    int cx, cy, cz;
    cell_of(q.x, q.y, q.z, cx, cy, cz);

    const int*    offs = g_offs + gsb * (CELLS + 1);
    const float4* pts  = g_sorted + (size_t)gsb * NPTS;

    // ---- Phase 1: full 3x3x3 neighborhood, 9 x-runs, bounds loaded upfront.
    // Border clamping may duplicate a row; min is idempotent so it's safe.
    int xlo = max(cx - 1, 0), xhi = min(cx + 1, G - 1);
    int aa[9], bb[9];
#pragma unroll
    for (int dz = 0; dz < 3; ++dz) {
        int z = min(max(cz + dz - 1, 0), G - 1);
#pragma unroll
        for (int dy = 0; dy < 3; ++dy) {
            int y = min(max(cy + dy - 1, 0), G - 1);
            int rowb = (z * G + y) * G;
            aa[dz * 3 + dy] = offs[rowb + xlo];
            bb[dz * 3 + dy] = offs[rowb + xhi + 1];
        }
    }

    float best = FINF;
#pragma unroll
    for (int k = 0; k < 9; ++k) {
        int s = aa[k], e = bb[k];
        // 4-unrolled: 4 independent loads + independent d2s per iteration
        for (; s + 4 <= e; s += 4) {
            float4 p0 = pts[s + 0];
            float4 p1 = pts[s + 1];
            float4 p2 = pts[s + 2];
            float4 p3 = pts[s + 3];
            float d0 = dist2(q, p0);
            float d1 = dist2(q, p1);
            float d2 = dist2(q, p2);
            float d3 = dist2(q, p3);
            best = fminf(best, fminf(fminf(d0, d1), fminf(d2, d3)));
        }
        for (; s < e; ++s)
            best = fminf(best, dist2(q, pts[s]));
    }

    // ---- Phase 2: rare. After the 27-cell scan every unscanned point is
    // >= HCELL away, so best <= HCELL^2 proves the exact minimum.
    if (best > HCELL * HCELL) {
        for (int r = 2; r <= G; ++r) {
            int zlo = max(cz - r, 0), zhi = min(cz + r, G - 1);
            for (int z = zlo; z <= zhi; ++z) {
                int adz = abs(z - cz);
                int ylo = max(cy - r, 0), yhi = min(cy + r, G - 1);
                for (int y = ylo; y <= yhi; ++y) {
                    int ady  = abs(y - cy);
                    int rowb = (z * G + y) * G;
                    if (adz == r || ady == r) {
                        int rxlo = max(cx - r, 0), rxhi = min(cx + r, G - 1);
                        int s0 = offs[rowb + rxlo];
                        int s1 = offs[rowb + rxhi + 1];
                        for (int s = s0; s < s1; ++s)
                            best = fminf(best, dist2(q, pts[s]));
                    } else {
#pragma unroll
                        for (int e2 = 0; e2 < 2; ++e2) {
                            int x = (e2 == 0) ? cx - r : cx + r;
                            if (x < 0 || x >= G) continue;
                            int c  = rowb + x;
                            int s0 = offs[c], s1 = offs[c + 1];
                            for (int s = s0; s < s1; ++s)
                                best = fminf(best, dist2(q, pts[s]));
                        }
                    }
                }
            }
            float rb = (float)r * HCELL;
            if (best <= rb * rb) break;   // unscanned cells >= r*h away
        }
    }

    int orig = __float_as_int(q.w);
    g_minbuf[qsb * NPTS + orig] = best;
}

// 6. deterministic block-tree partial sums
__global__ __launch_bounds__(256)
void k_reduce() {
    __shared__ float red[256];
    int i = blockIdx.x * 256 + threadIdx.x;
    red[threadIdx.x] = g_minbuf[i];
    __syncthreads();
#pragma unroll
    for (int s = 128; s > 0; s >>= 1) {
        if (threadIdx.x < s) red[threadIdx.x] += red[threadIdx.x + s];
        __syncthreads();
    }
    if (threadIdx.x == 0) g_blocksums[blockIdx.x] = red[0];
}

// 7. final: sum 512 partials; both means share denominator BATCH*NPTS
__global__ void k_final(float* __restrict__ out) {
    __shared__ float red[512];
    red[threadIdx.x] = g_blocksums[threadIdx.x];
    __syncthreads();
#pragma unroll
    for (int s = 256; s > 0; s >>= 1) {
        if (threadIdx.x < s) red[threadIdx.x] += red[threadIdx.x + s];
        __syncthreads();
    }
    if (threadIdx.x == 0)
        out[0] = red[0] / (float)(BATCH * NPTS);
}

extern "C" void kernel_launch(void* const* d_in, const int* in_sizes, int n_in,
                              void* d_out, int out_size) {
    const float* gts   = (const float*)d_in[0];
    const float* preds = (const float*)d_in[1];
    (void)in_sizes; (void)n_in; (void)out_size;

    k_zero<<<512, 256>>>();
    k_count<<<NTOT / 256, 256>>>(gts, preds);
    k_scan<<<NSB, 1024>>>();
    k_scatter<<<NTOT / 256, 256>>>(gts, preds);
    k_query<<<NTOT / 256, 256>>>();
    k_reduce<<<NTOT / 256, 256>>>();
    k_final<<<1, 512>>>((float*)d_out);
}

// round 13
// speedup vs baseline: 1.0830x; 1.0830x over previous
#include <cuda_runtime.h>

// ChamferLoss: B=8, N=M=8192, D=3 fp32, inputs ~ N(0,1).
// out = mean_n min_m ||gt_n - pred_m||^2 + mean_m min_n ||pred_m - gt_n||^2
//
// Grid-accelerated exact NN. R12 finding: the cost is NOT candidate evals
// (~34M ~= 12us of issue) but phase-2 tail queries enumerating EMPTY cells
// with serial L2 offs loads. R12 change: per-(side,batch) nonempty-cell
// bitmask (one uint32 per x-row, 4KB/sb) staged in shared memory per query
// block. Ring scans test row words from shared and only touch offs/points
// for set bits; phase 1 also tightens each 3-cell run to [first,last]
// nonempty cell. Exact min preserved; deterministic fixed-order reduction.

#define BATCH   8
#define NPTS    8192
#define G       32
#define CELLS   (G * G * G)
#define NROWS   (G * G)                // 1024 bitmask words per sb
#define NSB     (2 * BATCH)            // (side,batch); side 0=gts 1=preds
#define RANGE   6.0f                   // grid covers [-6,6]^3; max|coord|~4.7
#define HCELL   (2.0f * RANGE / G)     // 0.375
#define INVH    ((float)G / (2.0f * RANGE))
#define NTOT    (NSB * NPTS)           // 131072
#define FINF    3.402823466e+38f

__device__ int      g_count [NSB * CELLS];
__device__ int      g_cursor[NSB * CELLS];
__device__ int      g_offs  [NSB * (CELLS + 1)];
__device__ unsigned g_bits  [NSB * NROWS];       // nonempty-cell bitmask
__device__ float4   g_sorted[NSB * NPTS];        // cell-sorted, .w = orig idx
__device__ float    g_minbuf[NSB * NPTS];        // min d2 by original index
__device__ float    g_blocksums[512];

__device__ __forceinline__ int cell_of(float x, float y, float z,
                                       int& cx, int& cy, int& cz) {
    cx = min(G - 1, max(0, (int)floorf((x + RANGE) * INVH)));
    cy = min(G - 1, max(0, (int)floorf((y + RANGE) * INVH)));
    cz = min(G - 1, max(0, (int)floorf((z + RANGE) * INVH)));
    return (cz * G + cy) * G + cx;
}

__device__ __forceinline__ float dist2(float4 q, float4 p) {
    float dx = q.x - p.x, dy = q.y - p.y, dz = q.z - p.z;
    return dx * dx + dy * dy + dz * dz;
}

// bits lo..hi inclusive (0 <= lo <= hi <= 31)
__device__ __forceinline__ unsigned range_mask(int lo, int hi) {
    unsigned m = (hi >= 31) ? 0xFFFFFFFFu : ((1u << (hi + 1)) - 1u);
    return m & ~((1u << lo) - 1u);
}

// 1. zero counts, cursors, bitmask
__global__ __launch_bounds__(256)
void k_zero() {
    int i = blockIdx.x * 256 + threadIdx.x;
    int n = NSB * CELLS;
    int tot = 2 * n + NSB * NROWS;
    for (; i < tot; i += gridDim.x * 256) {
        if (i < n)          g_count[i] = 0;
        else if (i < 2 * n) g_cursor[i - n] = 0;
        else                g_bits[i - 2 * n] = 0u;
    }
}

// 2. count points per cell + mark nonempty rows
__global__ __launch_bounds__(256)
void k_count(const float* __restrict__ gts, const float* __restrict__ preds) {
    int idx = blockIdx.x * 256 + threadIdx.x;
    int sb  = idx >> 13;
    int i   = idx & (NPTS - 1);
    int side = sb >> 3, b = sb & 7;
    const float* p = (side == 0 ? gts : preds) + ((size_t)b * NPTS + i) * 3;
    int cx, cy, cz;
    int c = cell_of(p[0], p[1], p[2], cx, cy, cz);
    atomicAdd(&g_count[sb * CELLS + c], 1);
    atomicOr(&g_bits[sb * NROWS + (cz * G + cy)], 1u << cx);
}

// 3. exclusive prefix sum per (side,batch): 16 blocks x 1024 threads
__global__ __launch_bounds__(1024)
void k_scan() {
    const int sb = blockIdx.x;
    const int t  = threadIdx.x;
    const int base = sb * CELLS + t * 32;

    int s = 0;
#pragma unroll
    for (int k = 0; k < 32; ++k) s += g_count[base + k];

    __shared__ int ws[32];
    int lane = t & 31, wid = t >> 5;
    int v = s;
#pragma unroll
    for (int d = 1; d < 32; d <<= 1) {
        int n = __shfl_up_sync(0xFFFFFFFFu, v, d);
        if (lane >= d) v += n;
    }
    if (lane == 31) ws[wid] = v;
    __syncthreads();
    if (wid == 0) {
        int w = ws[lane];
#pragma unroll
        for (int d = 1; d < 32; d <<= 1) {
            int n = __shfl_up_sync(0xFFFFFFFFu, w, d);
            if (lane >= d) w += n;
        }
        ws[lane] = w;
    }
    __syncthreads();
    int excl = v - s + (wid ? ws[wid - 1] : 0);

    int run = excl;
    int obase = sb * (CELLS + 1) + t * 32;
#pragma unroll
    for (int k = 0; k < 32; ++k) {
        g_offs[obase + k] = run;
        run += g_count[base + k];
    }
    if (t == 1023) g_offs[sb * (CELLS + 1) + CELLS] = run;
}

// 4. scatter points into cell-sorted order
__global__ __launch_bounds__(256)
void k_scatter(const float* __restrict__ gts, const float* __restrict__ preds) {
    int idx = blockIdx.x * 256 + threadIdx.x;
    int sb  = idx >> 13;
    int i   = idx & (NPTS - 1);
    int side = sb >> 3, b = sb & 7;
    const float* p = (side == 0 ? gts : preds) + ((size_t)b * NPTS + i) * 3;
    float x = p[0], y = p[1], z = p[2];
    int cx, cy, cz;
    int c = cell_of(x, y, z, cx, cy, cz);
    int pos = g_offs[sb * (CELLS + 1) + c] + atomicAdd(&g_cursor[sb * CELLS + c], 1);
    g_sorted[sb * NPTS + pos] = make_float4(x, y, z, __int_as_float(i));
}

// 5. exact NN query: bitmask-pruned two-phase.
//    Each block serves one qsb (32 blocks per sb), so the OTHER side's 4KB
//    bitmask is staged in shared once per block.
__global__ __launch_bounds__(256)
void k_query() {
    __shared__ unsigned sbits[NROWS];

    int idx  = blockIdx.x * 256 + threadIdx.x;
    int qsb  = idx >> 13;
    int slot = idx & (NPTS - 1);
    int gsb  = qsb ^ 8;

#pragma unroll
    for (int k = 0; k < NROWS / 256; ++k)
        sbits[threadIdx.x + k * 256] = g_bits[gsb * NROWS + threadIdx.x + k * 256];
    __syncthreads();

    float4 q = g_sorted[qsb * NPTS + slot];
    int cx, cy, cz;
    cell_of(q.x, q.y, q.z, cx, cy, cz);

    const int*    offs = g_offs + gsb * (CELLS + 1);
    const float4* pts  = g_sorted + (size_t)gsb * NPTS;

    float best = FINF;

    // ---- Phase 1: 3x3x3 neighborhood, rows pruned/tightened by bitmask.
    {
        unsigned xm = range_mask(max(cx - 1, 0), min(cx + 1, G - 1));
#pragma unroll
        for (int dz = 0; dz < 3; ++dz) {
            int z = min(max(cz + dz - 1, 0), G - 1);
#pragma unroll
            for (int dy = 0; dy < 3; ++dy) {
                int y   = min(max(cy + dy - 1, 0), G - 1);
                int row = z * G + y;
                unsigned m = sbits[row] & xm;
                if (!m) continue;
                int x0 = __ffs(m) - 1;
                int x1 = 31 - __clz(m);
                int s  = offs[row * G + x0];
                int e  = offs[row * G + x1 + 1];
                for (; s + 4 <= e; s += 4) {
                    float4 p0 = pts[s + 0];
                    float4 p1 = pts[s + 1];
                    float4 p2 = pts[s + 2];
                    float4 p3 = pts[s + 3];
                    best = fminf(best,
                           fminf(fminf(dist2(q, p0), dist2(q, p1)),
                                 fminf(dist2(q, p2), dist2(q, p3))));
                }
                for (; s < e; ++s)
                    best = fminf(best, dist2(q, pts[s]));
            }
        }
    }

    // ---- Phase 2: rare tail. Ring scan with bitmask pruning: test the row
    // word (shared, cheap) and only touch offs/points for set bits. After
    // finishing ring r every unscanned point is >= r*HCELL away -> exact.
    if (best > HCELL * HCELL) {
        for (int r = 2; r <= G; ++r) {
            int zlo = max(cz - r, 0), zhi = min(cz + r, G - 1);
            for (int z = zlo; z <= zhi; ++z) {
                int adz = abs(z - cz);
                int ylo = max(cy - r, 0), yhi = min(cy + r, G - 1);
                for (int y = ylo; y <= yhi; ++y) {
                    int ady = abs(y - cy);
                    int row = z * G + y;
                    unsigned m;
                    if (adz == r || ady == r) {
                        m = sbits[row] &
                            range_mask(max(cx - r, 0), min(cx + r, G - 1));
                    } else {
                        unsigned em = 0;
                        if (cx - r >= 0) em |= 1u << (cx - r);
                        if (cx + r < G)  em |= 1u << (cx + r);
                        m = sbits[row] & em;
                    }
                    while (m) {
                        int x = __ffs(m) - 1;
                        m &= m - 1;
                        int c  = row * G + x;
                        int s0 = offs[c], s1 = offs[c + 1];
                        for (int s = s0; s < s1; ++s)
                            best = fminf(best, dist2(q, pts[s]));
                    }
                }
            }
            float rb = (float)r * HCELL;
            if (best <= rb * rb) break;
        }
    }

    int orig = __float_as_int(q.w);
    g_minbuf[qsb * NPTS + orig] = best;
}

// 6. deterministic block-tree partial sums (fixed index order)
__global__ __launch_bounds__(256)
void k_reduce() {
    __shared__ float red[256];
    int i = blockIdx.x * 256 + threadIdx.x;
    red[threadIdx.x] = g_minbuf[i];
    __syncthreads();
#pragma unroll
    for (int s = 128; s > 0; s >>= 1) {
        if (threadIdx.x < s) red[threadIdx.x] += red[threadIdx.x + s];
        __syncthreads();
    }
    if (threadIdx.x == 0) g_blocksums[blockIdx.x] = red[0];
}

// 7. final: sum 512 partials; both means share denominator BATCH*NPTS
__global__ void k_final(float* __restrict__ out) {
    __shared__ float red[512];
    red[threadIdx.x] = g_blocksums[threadIdx.x];
    __syncthreads();
#pragma unroll
    for (int s = 256; s > 0; s >>= 1) {
        if (threadIdx.x < s) red[threadIdx.x] += red[threadIdx.x + s];
        __syncthreads();
    }
    if (threadIdx.x == 0)
        out[0] = red[0] / (float)(BATCH * NPTS);
}

extern "C" void kernel_launch(void* const* d_in, const int* in_sizes, int n_in,
                              void* d_out, int out_size) {
    const float* gts   = (const float*)d_in[0];
    const float* preds = (const float*)d_in[1];
    (void)in_sizes; (void)n_in; (void)out_size;

    k_zero<<<512, 256>>>();
    k_count<<<NTOT / 256, 256>>>(gts, preds);
    k_scan<<<NSB, 1024>>>();
    k_scatter<<<NTOT / 256, 256>>>(gts, preds);
    k_query<<<NTOT / 256, 256>>>();
    k_reduce<<<NTOT / 256, 256>>>();
    k_final<<<1, 512>>>((float*)d_out);
}